// round 2
// baseline (speedup 1.0000x reference)
#include <cuda_runtime.h>
#include <cuda_fp16.h>
#include <cstdint>
#include <cstddef>

#define BATCH 8192
#define DIN   4096
#define DOUT  4096

// fp16 scratch (module-load allocation; legal per harness rules)
__device__ __half g_Xh[(size_t)BATCH * DIN];   // 64 MB
__device__ __half g_Wh[(size_t)DOUT  * DIN];   // 32 MB

// ---------------------------------------------------------------------------
// Conversion kernels: fp32 -> fp16 (x), fp32*mask -> fp16 (w)
// ---------------------------------------------------------------------------
__global__ void convert_x_kernel(const float4* __restrict__ x, int n4) {
    int i = blockIdx.x * blockDim.x + threadIdx.x;
    if (i >= n4) return;
    float4 v = x[i];
    __half2 h0 = __floats2half2_rn(v.x, v.y);
    __half2 h1 = __floats2half2_rn(v.z, v.w);
    uint2 u;
    u.x = *reinterpret_cast<uint32_t*>(&h0);
    u.y = *reinterpret_cast<uint32_t*>(&h1);
    reinterpret_cast<uint2*>(g_Xh)[i] = u;
}

__global__ void convert_w_kernel(const float4* __restrict__ w,
                                 const float4* __restrict__ m, int n4) {
    int i = blockIdx.x * blockDim.x + threadIdx.x;
    if (i >= n4) return;
    float4 wv = w[i];
    float4 mv = m[i];
    __half2 h0 = __floats2half2_rn(wv.x * mv.x, wv.y * mv.y);
    __half2 h1 = __floats2half2_rn(wv.z * mv.z, wv.w * mv.w);
    uint2 u;
    u.x = *reinterpret_cast<uint32_t*>(&h0);
    u.y = *reinterpret_cast<uint32_t*>(&h1);
    reinterpret_cast<uint2*>(g_Wh)[i] = u;
}

// ---------------------------------------------------------------------------
// GEMM: out[8192,4096] = Xh @ Wh^T, fp16 in / fp32 accum via mma.sync.m16n8k16
// CTA tile 128x128x32, 8 warps (4M x 2N), warp tile 32x64, 5-stage cp.async.
// ---------------------------------------------------------------------------
static constexpr int STAGES  = 5;
static constexpr int STAGE_B = 16384;              // A 8KB + B 8KB
static constexpr int SMEM_B  = STAGES * STAGE_B;   // 80 KB

// 64B rows (32 halfs). 16B chunk c in 0..3, swizzled so ldmatrix is
// conflict-free: bank pattern repeats every 2 rows, so XOR with (row>>1)&3.
__device__ __forceinline__ uint32_t sw_off(int row, int c16) {
    return (uint32_t)(row * 64 + (((c16 ^ ((row >> 1) & 3)) << 4)));
}

__device__ __forceinline__ uint32_t smem_u32(const void* p) {
    uint32_t a;
    asm("{ .reg .u64 t; cvta.to.shared.u64 t, %1; cvt.u32.u64 %0, t; }"
        : "=r"(a) : "l"(p));
    return a;
}

__device__ __forceinline__ void ldsm_x4(uint32_t& r0, uint32_t& r1,
                                        uint32_t& r2, uint32_t& r3, uint32_t addr) {
    asm volatile("ldmatrix.sync.aligned.m8n8.x4.shared.b16 {%0,%1,%2,%3}, [%4];"
                 : "=r"(r0), "=r"(r1), "=r"(r2), "=r"(r3) : "r"(addr));
}

__device__ __forceinline__ void mma16816(float* c, const uint32_t* a,
                                         uint32_t b0, uint32_t b1) {
    asm volatile(
        "mma.sync.aligned.m16n8k16.row.col.f32.f16.f16.f32 "
        "{%0,%1,%2,%3}, {%4,%5,%6,%7}, {%8,%9}, {%0,%1,%2,%3};"
        : "+f"(c[0]), "+f"(c[1]), "+f"(c[2]), "+f"(c[3])
        : "r"(a[0]), "r"(a[1]), "r"(a[2]), "r"(a[3]), "r"(b0), "r"(b1));
}

__device__ __forceinline__ void load_stage(uint32_t st_base, int slot,
                                           int k0, int m0, int n0, int tid) {
    uint32_t base = st_base + (uint32_t)slot * STAGE_B;
#pragma unroll
    for (int i = 0; i < 4; i++) {
        int cid = i * 256 + tid;            // 0..1023
        const __half* gp;
        uint32_t so;
        if (cid < 512) {                    // A: 128 rows x 4 chunks
            int row = cid >> 2, c = cid & 3;
            gp = g_Xh + (size_t)(m0 + row) * DIN + k0 + c * 8;
            so = base + sw_off(row, c);
        } else {                            // B: 128 rows x 4 chunks
            int row = (cid - 512) >> 2, c = cid & 3;
            gp = g_Wh + (size_t)(n0 + row) * DIN + k0 + c * 8;
            so = base + 8192 + sw_off(row, c);
        }
        asm volatile("cp.async.cg.shared.global [%0], [%1], 16;"
                     :: "r"(so), "l"(gp) : "memory");
    }
    asm volatile("cp.async.commit_group;" ::: "memory");
}

__global__ void __launch_bounds__(256, 2)
expander_gemm_kernel(float* __restrict__ out) {
    extern __shared__ char smem_raw[];
    const uint32_t st_base = smem_u32(smem_raw);

    const int tid  = threadIdx.x;
    const int lane = tid & 31;
    const int warp = tid >> 5;
    const int wm = warp & 3;        // 4 warps along M
    const int wn = warp >> 2;       // 2 warps along N
    const int mbase = wm * 32;
    const int nbase = wn * 64;

    // Rasterization: groups of 8 M-tiles x all 32 N-tiles for L2 reuse.
    const int TILES_N = DOUT / 128;               // 32
    const int per_g = 8 * TILES_N;                // 256
    int g   = blockIdx.x / per_g;
    int rem = blockIdx.x % per_g;
    int mt = g * 8 + (rem & 7);
    int nt = rem >> 3;
    const int m0 = mt * 128, n0 = nt * 128;

    // Per-thread ldmatrix addressing components.
    // A (x4): lanes 0-15 -> rows 0..15, lanes 16-31 -> same rows, next 16B chunk
    const int a_row  = lane & 15;
    const int a_cadd = lane >> 4;
    // B (x4): m0=(n0-7,c), m1=(n8-15,c), m2=(n0-7,c+1), m3=(n8-15,c+1)
    const int b_row  = (lane & 7) + ((lane >> 3) & 1) * 8;
    const int b_cadd = lane >> 4;

    // Precompute swizzle xor + row byte offsets (rows fixed per thread).
    int rA0 = mbase + a_row,        rA1 = mbase + 16 + a_row;
    uint32_t offA0 = (uint32_t)rA0 * 64, offA1 = (uint32_t)rA1 * 64;
    int xA0 = (rA0 >> 1) & 3,       xA1 = (rA1 >> 1) & 3;
    uint32_t offB[4]; int xB[4];
#pragma unroll
    for (int i4 = 0; i4 < 4; i4++) {
        int r = nbase + i4 * 16 + b_row;
        offB[i4] = 8192u + (uint32_t)r * 64;
        xB[i4]   = (r >> 1) & 3;
    }

    float acc[2][8][4];
#pragma unroll
    for (int a = 0; a < 2; a++)
#pragma unroll
        for (int b = 0; b < 8; b++)
#pragma unroll
            for (int c = 0; c < 4; c++) acc[a][b][c] = 0.f;

    // Prologue: fill 4 stages.
#pragma unroll
    for (int s = 0; s < STAGES - 1; s++)
        load_stage(st_base, s, s * 32, m0, n0, tid);

    const int NSTEPS = DIN / 32;    // 128
#pragma unroll 1
    for (int ks = 0; ks < NSTEPS; ks++) {
        asm volatile("cp.async.wait_group 3;" ::: "memory");
        __syncthreads();

        // Refill the slot consumed last iteration.
        int nxt = ks + STAGES - 1;
        if (nxt < NSTEPS)
            load_stage(st_base, nxt % STAGES, nxt * 32, m0, n0, tid);

        const uint32_t sb = st_base + (uint32_t)(ks % STAGES) * STAGE_B;

#pragma unroll
        for (int kk = 0; kk < 2; kk++) {
            const int ca = kk * 2 + a_cadd;
            const int cb = kk * 2 + b_cadd;
            uint32_t A0[4], A1[4];
            ldsm_x4(A0[0], A0[1], A0[2], A0[3], sb + offA0 + ((uint32_t)(ca ^ xA0) << 4));
            ldsm_x4(A1[0], A1[1], A1[2], A1[3], sb + offA1 + ((uint32_t)(ca ^ xA1) << 4));
            uint32_t Bf[4][4];
#pragma unroll
            for (int i4 = 0; i4 < 4; i4++)
                ldsm_x4(Bf[i4][0], Bf[i4][1], Bf[i4][2], Bf[i4][3],
                        sb + offB[i4] + ((uint32_t)(cb ^ xB[i4]) << 4));
#pragma unroll
            for (int i4 = 0; i4 < 4; i4++) {
                mma16816(acc[0][i4 * 2 + 0], A0, Bf[i4][0], Bf[i4][2]);
                mma16816(acc[0][i4 * 2 + 1], A0, Bf[i4][1], Bf[i4][3]);
                mma16816(acc[1][i4 * 2 + 0], A1, Bf[i4][0], Bf[i4][2]);
                mma16816(acc[1][i4 * 2 + 1], A1, Bf[i4][1], Bf[i4][3]);
            }
        }
    }

    // Epilogue: direct stores, 8B (2 floats) per lane per fragment pair.
    const int gid = lane >> 2, tig = lane & 3;
#pragma unroll
    for (int im = 0; im < 2; im++) {
        int r0 = m0 + mbase + im * 16 + gid;
#pragma unroll
        for (int j8 = 0; j8 < 8; j8++) {
            int col = n0 + nbase + j8 * 8 + tig * 2;
            float2 v0 = make_float2(acc[im][j8][0], acc[im][j8][1]);
            float2 v1 = make_float2(acc[im][j8][2], acc[im][j8][3]);
            *reinterpret_cast<float2*>(out + (size_t)r0 * DOUT + col) = v0;
            *reinterpret_cast<float2*>(out + (size_t)(r0 + 8) * DOUT + col) = v1;
        }
    }
}

// ---------------------------------------------------------------------------
// Launch
// ---------------------------------------------------------------------------
extern "C" void kernel_launch(void* const* d_in, const int* in_sizes, int n_in,
                              void* d_out, int out_size) {
    const float* x    = (const float*)d_in[0];
    const float* w    = (const float*)d_in[1];
    const float* mask = (const float*)d_in[2];
    float* out = (float*)d_out;

    {
        int n4 = (BATCH * DIN) / 4;
        convert_x_kernel<<<(n4 + 255) / 256, 256>>>((const float4*)x, n4);
    }
    {
        int n4 = (DOUT * DIN) / 4;
        convert_w_kernel<<<(n4 + 255) / 256, 256>>>((const float4*)w, (const float4*)mask, n4);
    }

    static bool attr_set = false;
    if (!attr_set) {
        cudaFuncSetAttribute(expander_gemm_kernel,
                             cudaFuncAttributeMaxDynamicSharedMemorySize, SMEM_B);
        attr_set = true;
    }
    int grid = (BATCH / 128) * (DOUT / 128);   // 2048
    expander_gemm_kernel<<<grid, 256, SMEM_B>>>(out);
}